// round 3
// baseline (speedup 1.0000x reference)
#include <cuda_runtime.h>
#include <cuda_bf16.h>

#define HD    64      // hidden dim
#define G4    256     // 4*HD gates
#define PB    64      // peds per LSTM block
#define TPB   256
#define DCOL  544     // dist_fc_input width = 256 + 256 + 32
#define MLPW  32
#define ZS    32

typedef unsigned long long ull;

__device__ __forceinline__ ull pk2(float lo, float hi) {
    ull r; asm("mov.b64 %0,{%1,%2};" : "=l"(r) : "f"(lo), "f"(hi)); return r;
}
__device__ __forceinline__ float2 upk2(ull v) {
    float2 f; asm("mov.b64 {%0,%1},%2;" : "=f"(f.x), "=f"(f.y) : "l"(v)); return f;
}
// packed dual fp32 FMA (SASS FFMA2) — ptxas never emits this from C++
__device__ __forceinline__ ull ffma2(ull a, ull b, ull c) {
    ull d; asm("fma.rn.f32x2 %0,%1,%2,%3;" : "=l"(d) : "l"(a), "l"(b), "l"(c)); return d;
}

__device__ __forceinline__ float sigf(float x) { return 1.0f / (1.0f + __expf(-x)); }
__device__ __forceinline__ float tanhfast(float x) { return 2.0f / (1.0f + __expf(-2.0f * x)) - 1.0f; }

// ---------------------------------------------------------------------------
// K1: bidirectional LSTM. grid = (B/PB, 2); blockIdx.y = 0 fwd, 1 rev.
// Gate GEMM done in packed f32x2 (pairs along the gate-dim axis).
// smem: w_hh (64x256) | w_ih (2x256) | bias (256) | h_s (64x64, k-major)
// ---------------------------------------------------------------------------
__global__ void __launch_bounds__(TPB) lstm_kernel(
    const float* __restrict__ last_obs, const float* __restrict__ xseq,
    const float* __restrict__ w_h0, const float* __restrict__ b_h0,
    const float* __restrict__ w_c0, const float* __restrict__ b_c0,
    const float* __restrict__ w_ih_f, const float* __restrict__ w_hh_f, const float* __restrict__ b_f,
    const float* __restrict__ w_ih_r, const float* __restrict__ w_hh_r, const float* __restrict__ b_r,
    float* __restrict__ out, int B, int T)
{
    extern __shared__ float sm[];
    float* w_s   = sm;                    // 16384 floats
    float* wih_s = w_s + HD * G4;         // 512
    float* b_s   = wih_s + 2 * G4;        // 256
    float* h_s   = b_s + G4;              // 4096  (layout [k][p])

    const int rev = blockIdx.y;
    const float* w_hh = rev ? w_hh_r : w_hh_f;
    const float* w_ih = rev ? w_ih_r : w_ih_f;
    const float* bias = rev ? b_r    : b_f;

    const int tid = threadIdx.x;
    const int pb  = blockIdx.x * PB;

    for (int i = tid; i < (HD * G4) / 4; i += TPB)
        ((float4*)w_s)[i] = ((const float4*)w_hh)[i];
    for (int i = tid; i < (2 * G4) / 4; i += TPB)
        ((float4*)wih_s)[i] = ((const float4*)w_ih)[i];
    for (int i = tid; i < G4 / 4; i += TPB)
        ((float4*)b_s)[i] = ((const float4*)bias)[i];

    const int tp = tid & 15;   // ped group -> peds [tp*4, tp*4+4)
    const int td = tid >> 4;   // d group   -> dims [td*4, td*4+4)
    const int p0 = tp * 4;
    const int d0 = td * 4;

    float creg[4][4];   // [p][dd], persistent cell state

    if (!rev) {
        #pragma unroll
        for (int p = 0; p < 4; p++) {
            const float* lo = last_obs + (size_t)(pb + p0 + p) * 6;
            float l[6];
            #pragma unroll
            for (int k = 0; k < 6; k++) l[k] = lo[k];
            #pragma unroll
            for (int dd = 0; dd < 4; dd++) {
                const int d = d0 + dd;
                float ha = b_h0[d], ca = b_c0[d];
                #pragma unroll
                for (int k = 0; k < 6; k++) {
                    ha += l[k] * w_h0[k * HD + d];
                    ca += l[k] * w_c0[k * HD + d];
                }
                h_s[d * PB + p0 + p] = ha;
                creg[p][dd] = ca;
            }
        }
    } else {
        #pragma unroll
        for (int p = 0; p < 4; p++)
            #pragma unroll
            for (int dd = 0; dd < 4; dd++) {
                h_s[(d0 + dd) * PB + p0 + p] = 0.f;
                creg[p][dd] = 0.f;
            }
    }
    __syncthreads();

    for (int s = 0; s < T; s++) {
        const int t = rev ? (T - 1 - s) : s;

        // x inputs, duplicated into f32x2 lanes
        ull x0d[4], x1d[4];
        #pragma unroll
        for (int p = 0; p < 4; p++) {
            const float2 xv = ((const float2*)xseq)[(size_t)t * B + pb + p0 + p];
            x0d[p] = pk2(xv.x, xv.x);
            x1d[p] = pk2(xv.y, xv.y);
        }

        // packed accumulators: [p][gate][pair], pair covers dims (d0+2pr, d0+2pr+1)
        ull acc[4][4][2];
        #pragma unroll
        for (int g = 0; g < 4; g++)
            #pragma unroll
            for (int pr = 0; pr < 2; pr++) {
                const int j = g * HD + d0 + pr * 2;
                const ull bp   = *(const ull*)&b_s[j];
                const ull wi0p = *(const ull*)&wih_s[j];
                const ull wi1p = *(const ull*)&wih_s[G4 + j];
                #pragma unroll
                for (int p = 0; p < 4; p++)
                    acc[p][g][pr] = ffma2(x1d[p], wi1p, ffma2(x0d[p], wi0p, bp));
            }

        #pragma unroll 4
        for (int k = 0; k < HD; k++) {
            const float4 hv = *(const float4*)&h_s[k * PB + p0];
            ull hd[4];
            hd[0] = pk2(hv.x, hv.x); hd[1] = pk2(hv.y, hv.y);
            hd[2] = pk2(hv.z, hv.z); hd[3] = pk2(hv.w, hv.w);
            #pragma unroll
            for (int g = 0; g < 4; g++) {
                const ulonglong2 wp = *(const ulonglong2*)&w_s[k * G4 + g * HD + d0];
                #pragma unroll
                for (int p = 0; p < 4; p++) {
                    acc[p][g][0] = ffma2(hd[p], wp.x, acc[p][g][0]);
                    acc[p][g][1] = ffma2(hd[p], wp.y, acc[p][g][1]);
                }
            }
        }
        __syncthreads();   // all reads of h_s done

        float hn[4][4];    // [dd][p]
        #pragma unroll
        for (int p = 0; p < 4; p++) {
            #pragma unroll
            for (int pr = 0; pr < 2; pr++) {
                const float2 zi = upk2(acc[p][0][pr]);
                const float2 zf = upk2(acc[p][1][pr]);
                const float2 zg = upk2(acc[p][2][pr]);
                const float2 zo = upk2(acc[p][3][pr]);
                const int dd = pr * 2;
                float c0 = sigf(zf.x) * creg[p][dd] + sigf(zi.x) * tanhfast(zg.x);
                creg[p][dd] = c0;
                hn[dd][p] = sigf(zo.x) * tanhfast(c0);
                float c1 = sigf(zf.y) * creg[p][dd + 1] + sigf(zi.y) * tanhfast(zg.y);
                creg[p][dd + 1] = c1;
                hn[dd + 1][p] = sigf(zo.y) * tanhfast(c1);
            }
        }

        #pragma unroll
        for (int dd = 0; dd < 4; dd++)
            *(float4*)&h_s[(d0 + dd) * PB + p0] =
                make_float4(hn[dd][0], hn[dd][1], hn[dd][2], hn[dd][3]);
        __syncthreads();   // h_s updated for next step
    }

    const int cb = rev * HD;
    #pragma unroll
    for (int p = 0; p < 4; p++) {
        float* orow = out + (size_t)(pb + p0 + p) * DCOL;
        #pragma unroll
        for (int dd = 0; dd < 4; dd++) {
            orow[cb + d0 + dd]       = h_s[(d0 + dd) * PB + p0 + p];
            orow[128 + cb + d0 + dd] = creg[p][dd];
        }
    }
}

// ---------------------------------------------------------------------------
// K2: per-scene attention pooling, packed f32x2.
// ---------------------------------------------------------------------------
#define ESTR 260
#define ASTR 68

__global__ void __launch_bounds__(TPB) attn_kernel(float* __restrict__ out,
                                                   const float* __restrict__ obs)
{
    extern __shared__ float sm[];
    float* E = sm;               // 64 x ESTR
    float* A = E + 64 * ESTR;    // 64 x ASTR

    const int tid = threadIdx.x;
    const int pbase = blockIdx.x * 64;

    for (int i = tid; i < 64 * 64; i += TPB) {
        const int p = i >> 6, c4 = i & 63;
        ((float4*)&E[p * ESTR])[c4] =
            ((const float4*)(out + (size_t)(pbase + p) * DCOL))[c4];
    }
    __syncthreads();

    // gram: packed lane-wise products, horizontal add at the end
    {
        const int tq = tid & 15, tpp = tid >> 4;
        const int q0 = tq * 4, pg0 = tpp * 4;
        ull acc2[4][4];
        #pragma unroll
        for (int i = 0; i < 4; i++)
            #pragma unroll
            for (int j = 0; j < 4; j++) acc2[i][j] = 0ull;

        for (int d4 = 0; d4 < 64; d4++) {
            ulonglong2 av[4], bv[4];
            #pragma unroll
            for (int i = 0; i < 4; i++) av[i] = *(const ulonglong2*)&E[(pg0 + i) * ESTR + d4 * 4];
            #pragma unroll
            for (int i = 0; i < 4; i++) bv[i] = *(const ulonglong2*)&E[(q0 + i) * ESTR + d4 * 4];
            #pragma unroll
            for (int i = 0; i < 4; i++)
                #pragma unroll
                for (int j = 0; j < 4; j++) {
                    acc2[i][j] = ffma2(av[i].x, bv[j].x, acc2[i][j]);
                    acc2[i][j] = ffma2(av[i].y, bv[j].y, acc2[i][j]);
                }
        }
        #pragma unroll
        for (int i = 0; i < 4; i++)
            #pragma unroll
            for (int j = 0; j < 4; j++) {
                const float2 s = upk2(acc2[i][j]);
                A[(pg0 + i) * ASTR + q0 + j] = s.x + s.y;
            }
    }
    __syncthreads();

    if (tid < 64) {
        float m = -1e30f;
        for (int q = 0; q < 64; q++) m = fmaxf(m, A[tid * ASTR + q]);
        float ssum = 0.f;
        for (int q = 0; q < 64; q++) {
            const float e = __expf(A[tid * ASTR + q] - m);
            A[tid * ASTR + q] = e;
            ssum += e;
        }
        const float inv = 1.0f / ssum;
        for (int q = 0; q < 64; q++) A[tid * ASTR + q] *= inv;
    }
    __syncthreads();

    // pool: packed along d
    {
        const int tp2 = tid & 15, td2 = tid >> 4;
        const int pp0 = tp2 * 4, dd0 = td2 * 16;
        ull pacc[4][8];
        #pragma unroll
        for (int i = 0; i < 4; i++)
            #pragma unroll
            for (int r = 0; r < 8; r++) pacc[i][r] = 0ull;

        for (int q = 0; q < 64; q++) {
            ull ad[4];
            #pragma unroll
            for (int i = 0; i < 4; i++) {
                const float a = A[(pp0 + i) * ASTR + q];
                ad[i] = pk2(a, a);
            }
            ull ev[8];
            #pragma unroll
            for (int c4 = 0; c4 < 4; c4++) {
                const ulonglong2 e2 = *(const ulonglong2*)&E[q * ESTR + dd0 + c4 * 4];
                ev[c4 * 2] = e2.x; ev[c4 * 2 + 1] = e2.y;
            }
            #pragma unroll
            for (int i = 0; i < 4; i++)
                #pragma unroll
                for (int r = 0; r < 8; r++)
                    pacc[i][r] = ffma2(ad[i], ev[r], pacc[i][r]);
        }
        #pragma unroll
        for (int i = 0; i < 4; i++) {
            float* orow = out + (size_t)(pbase + pp0 + i) * DCOL + 256 + dd0;
            #pragma unroll
            for (int c4 = 0; c4 < 4; c4++) {
                ulonglong2 st;
                st.x = pacc[i][c4 * 2]; st.y = pacc[i][c4 * 2 + 1];
                *(ulonglong2*)&orow[c4 * 4] = st;
            }
        }
    }

    for (int i = tid; i < 64 * MLPW; i += TPB) {
        const int p = i >> 5, c = i & 31;
        out[(size_t)(pbase + p) * DCOL + 512 + c] = obs[(size_t)(pbase + p) * MLPW + c];
    }
}

// ---------------------------------------------------------------------------
// K3: stats = dist_fc_input @ w_fc2 + b_fc2, packed f32x2.
// ---------------------------------------------------------------------------
__global__ void __launch_bounds__(TPB) fc2_kernel(
    const float* __restrict__ dfi, const float* __restrict__ w,
    const float* __restrict__ bz, float* __restrict__ stats)
{
    extern __shared__ float ws[];   // 544*32
    const int tid = threadIdx.x;
    for (int i = tid; i < (DCOL * ZS) / 4; i += TPB)
        ((float4*)ws)[i] = ((const float4*)w)[i];
    __syncthreads();

    const int og = tid & 7, rl = tid >> 3;
    const int o0 = og * 4;
    const int rowbase = blockIdx.x * 256;
    const ull b01 = *(const ull*)&bz[o0];
    const ull b23 = *(const ull*)&bz[o0 + 2];

    for (int pass = 0; pass < 8; pass++) {
        const int row = rowbase + pass * 32 + rl;
        const float* dr = dfi + (size_t)row * DCOL;
        ull a01 = b01, a23 = b23;
        #pragma unroll 2
        for (int j = 0; j < DCOL; j += 4) {
            const float4 dv = __ldg((const float4*)(dr + j));
            const float dc[4] = {dv.x, dv.y, dv.z, dv.w};
            #pragma unroll
            for (int jj = 0; jj < 4; jj++) {
                const ull dd = pk2(dc[jj], dc[jj]);
                const ulonglong2 wv = *(const ulonglong2*)&ws[(j + jj) * ZS + o0];
                a01 = ffma2(dd, wv.x, a01);
                a23 = ffma2(dd, wv.y, a23);
            }
        }
        float* so = stats + (size_t)row * ZS + o0;
        *(ull*)&so[0] = a01;
        *(ull*)&so[2] = a23;
    }
}

// ---------------------------------------------------------------------------
extern "C" void kernel_launch(void* const* d_in, const int* in_sizes, int n_in,
                              void* d_out, int out_size)
{
    const float* last_obs = (const float*)d_in[0];
    const float* xseq     = (const float*)d_in[1];
    const float* obs      = (const float*)d_in[3];
    const float* w_h0     = (const float*)d_in[5];
    const float* b_h0     = (const float*)d_in[6];
    const float* w_c0     = (const float*)d_in[7];
    const float* b_c0     = (const float*)d_in[8];
    const float* w_ih_f   = (const float*)d_in[9];
    const float* w_hh_f   = (const float*)d_in[10];
    const float* b_f      = (const float*)d_in[11];
    const float* w_ih_r   = (const float*)d_in[12];
    const float* w_hh_r   = (const float*)d_in[13];
    const float* b_r      = (const float*)d_in[14];
    const float* w_fc2    = (const float*)d_in[15];
    const float* b_fc2    = (const float*)d_in[16];
    float* out = (float*)d_out;

    const int B = in_sizes[0] / 6;
    const int T = in_sizes[1] / (B * 2);
    const int S = in_sizes[2] / 2;

    const int smem_lstm = (HD * G4 + 2 * G4 + G4 + HD * PB) * 4;
    const int smem_attn = (64 * ESTR + 64 * ASTR) * 4;
    const int smem_fc2  = DCOL * ZS * 4;

    cudaFuncSetAttribute(lstm_kernel, cudaFuncAttributeMaxDynamicSharedMemorySize, smem_lstm);
    cudaFuncSetAttribute(attn_kernel, cudaFuncAttributeMaxDynamicSharedMemorySize, smem_attn);
    cudaFuncSetAttribute(fc2_kernel,  cudaFuncAttributeMaxDynamicSharedMemorySize, smem_fc2);

    dim3 g1(B / PB, 2);
    lstm_kernel<<<g1, TPB, smem_lstm>>>(last_obs, xseq,
                                        w_h0, b_h0, w_c0, b_c0,
                                        w_ih_f, w_hh_f, b_f,
                                        w_ih_r, w_hh_r, b_r,
                                        out, B, T);

    attn_kernel<<<S, TPB, smem_attn>>>(out, obs);

    float* stats = out + (size_t)B * DCOL;
    fc2_kernel<<<B / 256, TPB, smem_fc2>>>(out, w_fc2, b_fc2, stats);
}

// round 5
// speedup vs baseline: 2.0238x; 2.0238x over previous
#include <cuda_runtime.h>
#include <cuda_bf16.h>
#include <cstdint>

#define TPB   256
#define DCOL  544
#define MLPW  32
#define ZS    32

// ---- shared layout for LSTM (byte offsets), strides in bf16 units ----
#define ASTR   72            // h tile row stride (conflict-free for frag LDS)
#define AXSTR  40            // extras tile row stride
#define AB_SZ  (128 * ASTR * 2)        // 18432 B per split buffer
#define AX_SZ  (128 * AXSTR * 2)       // 10240 B
#define OFF_AHI0 0
#define OFF_ALO0 (OFF_AHI0 + AB_SZ)
#define OFF_AHI1 (OFF_ALO0 + AB_SZ)
#define OFF_ALO1 (OFF_AHI1 + AB_SZ)
#define OFF_AX0  (OFF_ALO1 + AB_SZ)
#define OFF_AX1  (OFF_AX0 + AX_SZ)
#define SMEM_LSTM (OFF_AX1 + AX_SZ)    // 94208 B

typedef unsigned short ush;

__device__ __forceinline__ void split_bf(float v, ush& hi, ush& lo) {
    __nv_bfloat16 h = __float2bfloat16(v);
    __nv_bfloat16 l = __float2bfloat16(v - __bfloat162float(h));
    hi = *(ush*)&h; lo = *(ush*)&l;
}
__device__ __forceinline__ uint32_t pk(ush a, ush b) {   // a = lower k index
    return (uint32_t)a | ((uint32_t)b << 16);
}
__device__ __forceinline__ void mma16816(float* c, const uint32_t* a, const uint32_t* b) {
    asm volatile("mma.sync.aligned.m16n8k16.row.col.f32.bf16.bf16.f32 "
        "{%0,%1,%2,%3},{%4,%5,%6,%7},{%8,%9},{%0,%1,%2,%3};"
        : "+f"(c[0]), "+f"(c[1]), "+f"(c[2]), "+f"(c[3])
        : "r"(a[0]), "r"(a[1]), "r"(a[2]), "r"(a[3]), "r"(b[0]), "r"(b[1]));
}
__device__ __forceinline__ float sigf(float x)  { return __fdividef(1.0f, 1.0f + __expf(-x)); }
__device__ __forceinline__ float tanhf_(float x){ return __fdividef(2.0f, 1.0f + __expf(-2.0f * x)) - 1.0f; }

// ---------------------------------------------------------------------------
// K1: bidirectional LSTM on HMMA (mma.sync bf16 split-precision).
// grid = (B/128, 2), 256 threads. Warp w owns hidden dims [8w, 8w+8) x 4 gates.
// ---------------------------------------------------------------------------
__global__ void __launch_bounds__(TPB, 1) lstm_mma_kernel(
    const float* __restrict__ last_obs, const float* __restrict__ xseq,
    const float* __restrict__ w_h0, const float* __restrict__ b_h0,
    const float* __restrict__ w_c0, const float* __restrict__ b_c0,
    const float* __restrict__ w_ih_f, const float* __restrict__ w_hh_f, const float* __restrict__ b_f,
    const float* __restrict__ w_ih_r, const float* __restrict__ w_hh_r, const float* __restrict__ b_r,
    float* __restrict__ out, int Bn, int T)
{
    extern __shared__ char sm[];
    const int tid = threadIdx.x, w = tid >> 5, lane = tid & 31;
    const int gl = lane >> 2, t2 = (lane & 3) * 2;
    const int rev = blockIdx.y, pb = blockIdx.x * 128;

    const float* w_hh = rev ? w_hh_r : w_hh_f;
    const float* w_ih = rev ? w_ih_r : w_ih_f;
    const float* bias = rev ? b_r    : b_f;

    // ---- B fragments in registers: [gate][ktile][reg] ----
    uint32_t Bhi[4][4][2], Blo[4][4][2], Bx[4][2];
#pragma unroll
    for (int g = 0; g < 4; g++) {
        const int col = g * 64 + 8 * w + gl;
#pragma unroll
        for (int kt = 0; kt < 4; kt++) {
            const int k0 = kt * 16 + t2;
            ush h0, l0, h1, l1, h2, l2, h3, l3;
            split_bf(w_hh[(k0    ) * 256 + col], h0, l0);
            split_bf(w_hh[(k0 + 1) * 256 + col], h1, l1);
            split_bf(w_hh[(k0 + 8) * 256 + col], h2, l2);
            split_bf(w_hh[(k0 + 9) * 256 + col], h3, l3);
            Bhi[g][kt][0] = pk(h0, h1); Bhi[g][kt][1] = pk(h2, h3);
            Blo[g][kt][0] = pk(l0, l1); Blo[g][kt][1] = pk(l2, l3);
        }
        // extras rows: [w0h, w0h, w0l, w1h, w1h, w1l, bh, bl], rows 8..15 zero
        ush w0h, w0l, w1h, w1l, bh, bl;
        split_bf(w_ih[col],       w0h, w0l);
        split_bf(w_ih[256 + col], w1h, w1l);
        split_bf(bias[col],       bh,  bl);
        uint32_t pr[4] = { pk(w0h, w0h), pk(w0l, w1h), pk(w1h, w1l), pk(bh, bl) };
        Bx[g][0] = pr[lane & 3];
        Bx[g][1] = 0u;
    }

    // ---- init h0/c0 and shared buffers ----
    float cst[8][4];   // cell state: [mtile][c-frag slot]
    {
        char* ahi0 = sm + OFF_AHI0;
        char* alo0 = sm + OFF_ALO0;
        if (!rev) {
#pragma unroll
            for (int mt = 0; mt < 8; mt++) {
#pragma unroll
                for (int rr = 0; rr < 2; rr++) {
                    const int m = mt * 16 + gl + rr * 8;
                    const float* lo = last_obs + (size_t)(pb + m) * 6;
                    float l6[6];
#pragma unroll
                    for (int k = 0; k < 6; k++) l6[k] = lo[k];
                    float hv[2];
#pragma unroll
                    for (int dd = 0; dd < 2; dd++) {
                        const int d = 8 * w + t2 + dd;
                        float hh = b_h0[d], cc = b_c0[d];
#pragma unroll
                        for (int k = 0; k < 6; k++) {
                            hh += l6[k] * w_h0[k * 64 + d];
                            cc += l6[k] * w_c0[k * 64 + d];
                        }
                        hv[dd] = hh;
                        cst[mt][rr * 2 + dd] = cc;
                    }
                    ush h0b, l0b, h1b, l1b;
                    split_bf(hv[0], h0b, l0b);
                    split_bf(hv[1], h1b, l1b);
                    const int off = m * (ASTR * 2) + (8 * w + t2) * 2;
                    *(uint32_t*)(ahi0 + off) = pk(h0b, h1b);
                    *(uint32_t*)(alo0 + off) = pk(l0b, l1b);
                }
            }
        } else {
#pragma unroll
            for (int mt = 0; mt < 8; mt++) {
#pragma unroll
                for (int rr = 0; rr < 2; rr++) {
                    const int m = mt * 16 + gl + rr * 8;
                    const int off = m * (ASTR * 2) + (8 * w + t2) * 2;
                    *(uint32_t*)(ahi0 + off) = 0u;
                    *(uint32_t*)(alo0 + off) = 0u;
                }
#pragma unroll
                for (int e = 0; e < 4; e++) cst[mt][e] = 0.f;
            }
        }
    }
    // extras buffer: row tid<128: write x(t0) cols 0..7; zero cols 8..15 both bufs
    if (tid < 128) {
        const int t0 = rev ? (T - 1) : 0;
        const float2 xv = ((const float2*)xseq)[(size_t)t0 * Bn + pb + tid];
        ush x0h, x0l, x1h, x1l;
        split_bf(xv.x, x0h, x0l);
        split_bf(xv.y, x1h, x1l);
        uint4 v;
        v.x = pk(x0h, x0l); v.y = pk(x0h, x1h);
        v.z = pk(x1l, x1h); v.w = pk(0x3F80u, 0x3F80u);
        char* ax0 = sm + OFF_AX0 + tid * (AXSTR * 2);
        char* ax1 = sm + OFF_AX1 + tid * (AXSTR * 2);
        *(uint4*)ax0 = v;
        *(uint4*)(ax0 + 16) = make_uint4(0, 0, 0, 0);
        *(uint4*)(ax1 + 16) = make_uint4(0, 0, 0, 0);
    }
    __syncthreads();

    const int cb = rev * 64;
    const int dlo = 8 * w + t2;

    for (int s = 0; s < T; s++) {
        const bool last = (s == T - 1);
        // prefetch next x into the other extras buffer
        if (!last && tid < 128) {
            const int tn = rev ? (T - 2 - s) : (s + 1);
            const float2 xv = ((const float2*)xseq)[(size_t)tn * Bn + pb + tid];
            ush x0h, x0l, x1h, x1l;
            split_bf(xv.x, x0h, x0l);
            split_bf(xv.y, x1h, x1l);
            uint4 v;
            v.x = pk(x0h, x0l); v.y = pk(x0h, x1h);
            v.z = pk(x1l, x1h); v.w = pk(0x3F80u, 0x3F80u);
            *(uint4*)(sm + (((s + 1) & 1) ? OFF_AX1 : OFF_AX0) + tid * (AXSTR * 2)) = v;
        }

        char* ahi = sm + ((s & 1) ? OFF_AHI1 : OFF_AHI0);
        char* alo = sm + ((s & 1) ? OFF_ALO1 : OFF_ALO0);
        char* ax  = sm + ((s & 1) ? OFF_AX1  : OFF_AX0);
        char* nhi = sm + ((s & 1) ? OFF_AHI0 : OFF_AHI1);
        char* nlo = sm + ((s & 1) ? OFF_ALO0 : OFF_ALO1);

#pragma unroll 1
        for (int mt = 0; mt < 8; mt++) {
            const int r0 = (mt * 16 + gl) * (ASTR * 2);
            const int r1 = (mt * 16 + gl + 8) * (ASTR * 2);

            uint32_t ahf[4][4];
#pragma unroll
            for (int kt = 0; kt < 4; kt++) {
                const int cA = (kt * 16 + t2) * 2;
                ahf[kt][0] = *(const uint32_t*)(ahi + r0 + cA);
                ahf[kt][1] = *(const uint32_t*)(ahi + r1 + cA);
                ahf[kt][2] = *(const uint32_t*)(ahi + r0 + cA + 16);
                ahf[kt][3] = *(const uint32_t*)(ahi + r1 + cA + 16);
            }

            float C[4][4];
#pragma unroll
            for (int g = 0; g < 4; g++)
#pragma unroll
                for (int e = 0; e < 4; e++) C[g][e] = 0.f;

            // term 1: A_hi * B_hi
#pragma unroll
            for (int kt = 0; kt < 4; kt++)
#pragma unroll
                for (int g = 0; g < 4; g++)
                    mma16816(C[g], ahf[kt], Bhi[g][kt]);

            // term 2: A_lo * B_hi (A_lo transient)
#pragma unroll
            for (int kt = 0; kt < 4; kt++) {
                uint32_t alf[4];
                const int cA = (kt * 16 + t2) * 2;
                alf[0] = *(const uint32_t*)(alo + r0 + cA);
                alf[1] = *(const uint32_t*)(alo + r1 + cA);
                alf[2] = *(const uint32_t*)(alo + r0 + cA + 16);
                alf[3] = *(const uint32_t*)(alo + r1 + cA + 16);
#pragma unroll
                for (int g = 0; g < 4; g++)
                    mma16816(C[g], alf, Bhi[g][kt]);
            }

            // term 3: A_hi * B_lo
#pragma unroll
            for (int kt = 0; kt < 4; kt++)
#pragma unroll
                for (int g = 0; g < 4; g++)
                    mma16816(C[g], ahf[kt], Blo[g][kt]);

            // extras: x*w_ih + bias
            {
                uint32_t axf[4];
                const int rx0 = (mt * 16 + gl) * (AXSTR * 2);
                const int rx1 = (mt * 16 + gl + 8) * (AXSTR * 2);
                const int cX = t2 * 2;
                axf[0] = *(const uint32_t*)(ax + rx0 + cX);
                axf[1] = *(const uint32_t*)(ax + rx1 + cX);
                axf[2] = *(const uint32_t*)(ax + rx0 + cX + 16);
                axf[3] = *(const uint32_t*)(ax + rx1 + cX + 16);
#pragma unroll
                for (int g = 0; g < 4; g++)
                    mma16816(C[g], axf, Bx[g]);
            }

            // epilogue: C[0]=i, C[1]=f, C[2]=g, C[3]=o
            float hv[4];
#pragma unroll
            for (int e = 0; e < 4; e++) {
                const float cn = sigf(C[1][e]) * cst[mt][e] + sigf(C[0][e]) * tanhf_(C[2][e]);
                cst[mt][e] = cn;
                hv[e] = sigf(C[3][e]) * tanhf_(cn);
            }

            if (!last) {
                ush h0b, l0b, h1b, l1b;
                const int off0 = r0 + dlo * 2;
                const int off1 = r1 + dlo * 2;
                split_bf(hv[0], h0b, l0b);
                split_bf(hv[1], h1b, l1b);
                *(uint32_t*)(nhi + off0) = pk(h0b, h1b);
                *(uint32_t*)(nlo + off0) = pk(l0b, l1b);
                split_bf(hv[2], h0b, l0b);
                split_bf(hv[3], h1b, l1b);
                *(uint32_t*)(nhi + off1) = pk(h0b, h1b);
                *(uint32_t*)(nlo + off1) = pk(l0b, l1b);
            } else {
                float* o0 = out + (size_t)(pb + mt * 16 + gl) * DCOL;
                float* o1 = out + (size_t)(pb + mt * 16 + gl + 8) * DCOL;
                *(float2*)&o0[cb + dlo]       = make_float2(hv[0], hv[1]);
                *(float2*)&o1[cb + dlo]       = make_float2(hv[2], hv[3]);
                *(float2*)&o0[128 + cb + dlo] = make_float2(cst[mt][0], cst[mt][1]);
                *(float2*)&o1[128 + cb + dlo] = make_float2(cst[mt][2], cst[mt][3]);
            }
        }
        __syncthreads();
    }
}

// ---------------------------------------------------------------------------
// K2: per-scene attention pooling (R1 version, proven).
// ---------------------------------------------------------------------------
#define ESTR 260
#define ASTR2 68

__global__ void __launch_bounds__(TPB) attn_kernel(float* __restrict__ out,
                                                   const float* __restrict__ obs)
{
    extern __shared__ float smf[];
    float* E = smf;
    float* A = E + 64 * ESTR;

    const int tid = threadIdx.x;
    const int pbase = blockIdx.x * 64;

    for (int i = tid; i < 64 * 64; i += TPB) {
        const int p = i >> 6, c4 = i & 63;
        ((float4*)&E[p * ESTR])[c4] =
            ((const float4*)(out + (size_t)(pbase + p) * DCOL))[c4];
    }
    __syncthreads();

    {
        const int tq = tid & 15, tpp = tid >> 4;
        const int q0 = tq * 4, pg0 = tpp * 4;
        float acc[4][4] = {};
        for (int d4 = 0; d4 < 64; d4++) {
            float4 av[4], bv[4];
#pragma unroll
            for (int i = 0; i < 4; i++) av[i] = *(const float4*)&E[(pg0 + i) * ESTR + d4 * 4];
#pragma unroll
            for (int i = 0; i < 4; i++) bv[i] = *(const float4*)&E[(q0 + i) * ESTR + d4 * 4];
#pragma unroll
            for (int i = 0; i < 4; i++)
#pragma unroll
                for (int j = 0; j < 4; j++)
                    acc[i][j] += av[i].x * bv[j].x + av[i].y * bv[j].y
                               + av[i].z * bv[j].z + av[i].w * bv[j].w;
        }
#pragma unroll
        for (int i = 0; i < 4; i++)
#pragma unroll
            for (int j = 0; j < 4; j++)
                A[(pg0 + i) * ASTR2 + q0 + j] = acc[i][j];
    }
    __syncthreads();

    if (tid < 64) {
        float m = -1e30f;
        for (int q = 0; q < 64; q++) m = fmaxf(m, A[tid * ASTR2 + q]);
        float ssum = 0.f;
        for (int q = 0; q < 64; q++) {
            const float e = __expf(A[tid * ASTR2 + q] - m);
            A[tid * ASTR2 + q] = e;
            ssum += e;
        }
        const float inv = 1.0f / ssum;
        for (int q = 0; q < 64; q++) A[tid * ASTR2 + q] *= inv;
    }
    __syncthreads();

    {
        const int tp2 = tid & 15, td2 = tid >> 4;
        const int pp0 = tp2 * 4, dd0 = td2 * 16;
        float pacc[4][16] = {};
        for (int q = 0; q < 64; q++) {
            float a4[4];
#pragma unroll
            for (int i = 0; i < 4; i++) a4[i] = A[(pp0 + i) * ASTR2 + q];
#pragma unroll
            for (int c4 = 0; c4 < 4; c4++) {
                const float4 ev = *(const float4*)&E[q * ESTR + dd0 + c4 * 4];
#pragma unroll
                for (int i = 0; i < 4; i++) {
                    pacc[i][c4 * 4 + 0] += a4[i] * ev.x;
                    pacc[i][c4 * 4 + 1] += a4[i] * ev.y;
                    pacc[i][c4 * 4 + 2] += a4[i] * ev.z;
                    pacc[i][c4 * 4 + 3] += a4[i] * ev.w;
                }
            }
        }
#pragma unroll
        for (int i = 0; i < 4; i++) {
            float* orow = out + (size_t)(pbase + pp0 + i) * DCOL + 256 + dd0;
#pragma unroll
            for (int c4 = 0; c4 < 4; c4++)
                *(float4*)&orow[c4 * 4] = make_float4(
                    pacc[i][c4 * 4 + 0], pacc[i][c4 * 4 + 1],
                    pacc[i][c4 * 4 + 2], pacc[i][c4 * 4 + 3]);
        }
    }

    for (int i = tid; i < 64 * MLPW; i += TPB) {
        const int p = i >> 5, cc = i & 31;
        out[(size_t)(pbase + p) * DCOL + 512 + cc] = obs[(size_t)(pbase + p) * MLPW + cc];
    }
}

// ---------------------------------------------------------------------------
// K3: stats = dist_fc_input @ w_fc2 + b_fc2 (R1 version, proven).
// ---------------------------------------------------------------------------
__global__ void __launch_bounds__(TPB) fc2_kernel(
    const float* __restrict__ dfi, const float* __restrict__ w,
    const float* __restrict__ bz, float* __restrict__ stats)
{
    extern __shared__ float ws[];
    const int tid = threadIdx.x;
    for (int i = tid; i < (DCOL * ZS) / 4; i += TPB)
        ((float4*)ws)[i] = ((const float4*)w)[i];
    __syncthreads();

    const int og = tid & 7, rl = tid >> 3;
    const int o0 = og * 4;
    const int rowbase = blockIdx.x * 256;

    for (int pass = 0; pass < 8; pass++) {
        const int row = rowbase + pass * 32 + rl;
        const float* dr = dfi + (size_t)row * DCOL;
        float a0 = bz[o0], a1 = bz[o0 + 1], a2 = bz[o0 + 2], a3 = bz[o0 + 3];
#pragma unroll 4
        for (int j = 0; j < DCOL; j++) {
            const float d = __ldg(dr + j);
            const float4 wv = *(const float4*)&ws[j * ZS + o0];
            a0 += d * wv.x; a1 += d * wv.y; a2 += d * wv.z; a3 += d * wv.w;
        }
        float* so = stats + (size_t)row * ZS + o0;
        so[0] = a0; so[1] = a1; so[2] = a2; so[3] = a3;
    }
}

// ---------------------------------------------------------------------------
extern "C" void kernel_launch(void* const* d_in, const int* in_sizes, int n_in,
                              void* d_out, int out_size)
{
    const float* last_obs = (const float*)d_in[0];
    const float* xseq     = (const float*)d_in[1];
    const float* obs      = (const float*)d_in[3];
    const float* w_h0     = (const float*)d_in[5];
    const float* b_h0     = (const float*)d_in[6];
    const float* w_c0     = (const float*)d_in[7];
    const float* b_c0     = (const float*)d_in[8];
    const float* w_ih_f   = (const float*)d_in[9];
    const float* w_hh_f   = (const float*)d_in[10];
    const float* b_f      = (const float*)d_in[11];
    const float* w_ih_r   = (const float*)d_in[12];
    const float* w_hh_r   = (const float*)d_in[13];
    const float* b_r      = (const float*)d_in[14];
    const float* w_fc2    = (const float*)d_in[15];
    const float* b_fc2    = (const float*)d_in[16];
    float* out = (float*)d_out;

    const int B = in_sizes[0] / 6;
    const int T = in_sizes[1] / (B * 2);
    const int S = in_sizes[2] / 2;

    const int smem_attn = (64 * ESTR + 64 * ASTR2) * 4;
    const int smem_fc2  = DCOL * ZS * 4;

    cudaFuncSetAttribute(lstm_mma_kernel, cudaFuncAttributeMaxDynamicSharedMemorySize, SMEM_LSTM);
    cudaFuncSetAttribute(attn_kernel, cudaFuncAttributeMaxDynamicSharedMemorySize, smem_attn);
    cudaFuncSetAttribute(fc2_kernel,  cudaFuncAttributeMaxDynamicSharedMemorySize, smem_fc2);

    dim3 g1(B / 128, 2);
    lstm_mma_kernel<<<g1, TPB, SMEM_LSTM>>>(last_obs, xseq,
                                            w_h0, b_h0, w_c0, b_c0,
                                            w_ih_f, w_hh_f, b_f,
                                            w_ih_r, w_hh_r, b_r,
                                            out, B, T);

    attn_kernel<<<S, TPB, smem_attn>>>(out, obs);

    float* stats = out + (size_t)B * DCOL;
    fc2_kernel<<<B / 256, TPB, smem_fc2>>>(out, w_fc2, b_fc2, stats);
}

// round 6
// speedup vs baseline: 2.4031x; 1.1874x over previous
#include <cuda_runtime.h>
#include <cuda_bf16.h>
#include <cstdint>

#define TPB   256
#define DCOL  544
#define MLPW  32
#define ZS    32

// ---- shared layout for LSTM (byte offsets), strides in bf16 units ----
#define ASTR   72            // h tile row stride (conflict-free for frag LDS)
#define AXSTR  40            // extras tile row stride
#define AB_SZ  (128 * ASTR * 2)        // 18432 B per split buffer
#define AX_SZ  (128 * AXSTR * 2)       // 10240 B
#define OFF_AHI0 0
#define OFF_ALO0 (OFF_AHI0 + AB_SZ)
#define OFF_AHI1 (OFF_ALO0 + AB_SZ)
#define OFF_ALO1 (OFF_AHI1 + AB_SZ)
#define OFF_AX0  (OFF_ALO1 + AB_SZ)
#define OFF_AX1  (OFF_AX0 + AX_SZ)
#define SMEM_LSTM (OFF_AX1 + AX_SZ)    // 94208 B

typedef unsigned short ush;

__device__ __forceinline__ uint32_t smem_u32(const void* p) {
    uint32_t a;
    asm("{ .reg .u64 t; cvta.to.shared.u64 t,%1; cvt.u32.u64 %0,t; }" : "=r"(a) : "l"(p));
    return a;
}
__device__ __forceinline__ void split_bf(float v, ush& hi, ush& lo) {
    __nv_bfloat16 h = __float2bfloat16(v);
    __nv_bfloat16 l = __float2bfloat16(v - __bfloat162float(h));
    hi = *(ush*)&h; lo = *(ush*)&l;
}
__device__ __forceinline__ uint32_t pk(ush a, ush b) {   // a = lower k index
    return (uint32_t)a | ((uint32_t)b << 16);
}
__device__ __forceinline__ void mma16816(float* c, const uint32_t* a, const uint32_t* b) {
    asm volatile("mma.sync.aligned.m16n8k16.row.col.f32.bf16.bf16.f32 "
        "{%0,%1,%2,%3},{%4,%5,%6,%7},{%8,%9},{%0,%1,%2,%3};"
        : "+f"(c[0]), "+f"(c[1]), "+f"(c[2]), "+f"(c[3])
        : "r"(a[0]), "r"(a[1]), "r"(a[2]), "r"(a[3]), "r"(b[0]), "r"(b[1]));
}
__device__ __forceinline__ void ldsm4(uint32_t* r, uint32_t a) {
    asm volatile("ldmatrix.sync.aligned.m8n8.x4.shared.b16 {%0,%1,%2,%3},[%4];"
        : "=r"(r[0]), "=r"(r[1]), "=r"(r[2]), "=r"(r[3]) : "r"(a));
}
__device__ __forceinline__ void ldsm4t(uint32_t* r, uint32_t a) {
    asm volatile("ldmatrix.sync.aligned.m8n8.x4.trans.shared.b16 {%0,%1,%2,%3},[%4];"
        : "=r"(r[0]), "=r"(r[1]), "=r"(r[2]), "=r"(r[3]) : "r"(a));
}
__device__ __forceinline__ float sigf(float x)  { return __fdividef(1.0f, 1.0f + __expf(-x)); }
__device__ __forceinline__ float tanhf_(float x){ return __fdividef(2.0f, 1.0f + __expf(-2.0f * x)) - 1.0f; }

// ---------------------------------------------------------------------------
// K1: bidirectional LSTM on HMMA (mma.sync bf16 split-precision). UNCHANGED (R5).
// ---------------------------------------------------------------------------
__global__ void __launch_bounds__(TPB, 1) lstm_mma_kernel(
    const float* __restrict__ last_obs, const float* __restrict__ xseq,
    const float* __restrict__ w_h0, const float* __restrict__ b_h0,
    const float* __restrict__ w_c0, const float* __restrict__ b_c0,
    const float* __restrict__ w_ih_f, const float* __restrict__ w_hh_f, const float* __restrict__ b_f,
    const float* __restrict__ w_ih_r, const float* __restrict__ w_hh_r, const float* __restrict__ b_r,
    float* __restrict__ out, int Bn, int T)
{
    extern __shared__ char sm[];
    const int tid = threadIdx.x, w = tid >> 5, lane = tid & 31;
    const int gl = lane >> 2, t2 = (lane & 3) * 2;
    const int rev = blockIdx.y, pb = blockIdx.x * 128;

    const float* w_hh = rev ? w_hh_r : w_hh_f;
    const float* w_ih = rev ? w_ih_r : w_ih_f;
    const float* bias = rev ? b_r    : b_f;

    uint32_t Bhi[4][4][2], Blo[4][4][2], Bx[4][2];
#pragma unroll
    for (int g = 0; g < 4; g++) {
        const int col = g * 64 + 8 * w + gl;
#pragma unroll
        for (int kt = 0; kt < 4; kt++) {
            const int k0 = kt * 16 + t2;
            ush h0, l0, h1, l1, h2, l2, h3, l3;
            split_bf(w_hh[(k0    ) * 256 + col], h0, l0);
            split_bf(w_hh[(k0 + 1) * 256 + col], h1, l1);
            split_bf(w_hh[(k0 + 8) * 256 + col], h2, l2);
            split_bf(w_hh[(k0 + 9) * 256 + col], h3, l3);
            Bhi[g][kt][0] = pk(h0, h1); Bhi[g][kt][1] = pk(h2, h3);
            Blo[g][kt][0] = pk(l0, l1); Blo[g][kt][1] = pk(l2, l3);
        }
        ush w0h, w0l, w1h, w1l, bh, bl;
        split_bf(w_ih[col],       w0h, w0l);
        split_bf(w_ih[256 + col], w1h, w1l);
        split_bf(bias[col],       bh,  bl);
        uint32_t pr[4] = { pk(w0h, w0h), pk(w0l, w1h), pk(w1h, w1l), pk(bh, bl) };
        Bx[g][0] = pr[lane & 3];
        Bx[g][1] = 0u;
    }

    float cst[8][4];
    {
        char* ahi0 = sm + OFF_AHI0;
        char* alo0 = sm + OFF_ALO0;
        if (!rev) {
#pragma unroll
            for (int mt = 0; mt < 8; mt++) {
#pragma unroll
                for (int rr = 0; rr < 2; rr++) {
                    const int m = mt * 16 + gl + rr * 8;
                    const float* lo = last_obs + (size_t)(pb + m) * 6;
                    float l6[6];
#pragma unroll
                    for (int k = 0; k < 6; k++) l6[k] = lo[k];
                    float hv[2];
#pragma unroll
                    for (int dd = 0; dd < 2; dd++) {
                        const int d = 8 * w + t2 + dd;
                        float hh = b_h0[d], cc = b_c0[d];
#pragma unroll
                        for (int k = 0; k < 6; k++) {
                            hh += l6[k] * w_h0[k * 64 + d];
                            cc += l6[k] * w_c0[k * 64 + d];
                        }
                        hv[dd] = hh;
                        cst[mt][rr * 2 + dd] = cc;
                    }
                    ush h0b, l0b, h1b, l1b;
                    split_bf(hv[0], h0b, l0b);
                    split_bf(hv[1], h1b, l1b);
                    const int off = m * (ASTR * 2) + (8 * w + t2) * 2;
                    *(uint32_t*)(ahi0 + off) = pk(h0b, h1b);
                    *(uint32_t*)(alo0 + off) = pk(l0b, l1b);
                }
            }
        } else {
#pragma unroll
            for (int mt = 0; mt < 8; mt++) {
#pragma unroll
                for (int rr = 0; rr < 2; rr++) {
                    const int m = mt * 16 + gl + rr * 8;
                    const int off = m * (ASTR * 2) + (8 * w + t2) * 2;
                    *(uint32_t*)(ahi0 + off) = 0u;
                    *(uint32_t*)(alo0 + off) = 0u;
                }
#pragma unroll
                for (int e = 0; e < 4; e++) cst[mt][e] = 0.f;
            }
        }
    }
    if (tid < 128) {
        const int t0 = rev ? (T - 1) : 0;
        const float2 xv = ((const float2*)xseq)[(size_t)t0 * Bn + pb + tid];
        ush x0h, x0l, x1h, x1l;
        split_bf(xv.x, x0h, x0l);
        split_bf(xv.y, x1h, x1l);
        uint4 v;
        v.x = pk(x0h, x0l); v.y = pk(x0h, x1h);
        v.z = pk(x1l, x1h); v.w = pk(0x3F80u, 0x3F80u);
        char* ax0 = sm + OFF_AX0 + tid * (AXSTR * 2);
        char* ax1 = sm + OFF_AX1 + tid * (AXSTR * 2);
        *(uint4*)ax0 = v;
        *(uint4*)(ax0 + 16) = make_uint4(0, 0, 0, 0);
        *(uint4*)(ax1 + 16) = make_uint4(0, 0, 0, 0);
    }
    __syncthreads();

    const int cb = rev * 64;
    const int dlo = 8 * w + t2;

    for (int s = 0; s < T; s++) {
        const bool last = (s == T - 1);
        if (!last && tid < 128) {
            const int tn = rev ? (T - 2 - s) : (s + 1);
            const float2 xv = ((const float2*)xseq)[(size_t)tn * Bn + pb + tid];
            ush x0h, x0l, x1h, x1l;
            split_bf(xv.x, x0h, x0l);
            split_bf(xv.y, x1h, x1l);
            uint4 v;
            v.x = pk(x0h, x0l); v.y = pk(x0h, x1h);
            v.z = pk(x1l, x1h); v.w = pk(0x3F80u, 0x3F80u);
            *(uint4*)(sm + (((s + 1) & 1) ? OFF_AX1 : OFF_AX0) + tid * (AXSTR * 2)) = v;
        }

        char* ahi = sm + ((s & 1) ? OFF_AHI1 : OFF_AHI0);
        char* alo = sm + ((s & 1) ? OFF_ALO1 : OFF_ALO0);
        char* ax  = sm + ((s & 1) ? OFF_AX1  : OFF_AX0);
        char* nhi = sm + ((s & 1) ? OFF_AHI0 : OFF_AHI1);
        char* nlo = sm + ((s & 1) ? OFF_ALO0 : OFF_ALO1);

#pragma unroll 1
        for (int mt = 0; mt < 8; mt++) {
            const int r0 = (mt * 16 + gl) * (ASTR * 2);
            const int r1 = (mt * 16 + gl + 8) * (ASTR * 2);

            uint32_t ahf[4][4];
#pragma unroll
            for (int kt = 0; kt < 4; kt++) {
                const int cA = (kt * 16 + t2) * 2;
                ahf[kt][0] = *(const uint32_t*)(ahi + r0 + cA);
                ahf[kt][1] = *(const uint32_t*)(ahi + r1 + cA);
                ahf[kt][2] = *(const uint32_t*)(ahi + r0 + cA + 16);
                ahf[kt][3] = *(const uint32_t*)(ahi + r1 + cA + 16);
            }

            float C[4][4];
#pragma unroll
            for (int g = 0; g < 4; g++)
#pragma unroll
                for (int e = 0; e < 4; e++) C[g][e] = 0.f;

#pragma unroll
            for (int kt = 0; kt < 4; kt++)
#pragma unroll
                for (int g = 0; g < 4; g++)
                    mma16816(C[g], ahf[kt], Bhi[g][kt]);

#pragma unroll
            for (int kt = 0; kt < 4; kt++) {
                uint32_t alf[4];
                const int cA = (kt * 16 + t2) * 2;
                alf[0] = *(const uint32_t*)(alo + r0 + cA);
                alf[1] = *(const uint32_t*)(alo + r1 + cA);
                alf[2] = *(const uint32_t*)(alo + r0 + cA + 16);
                alf[3] = *(const uint32_t*)(alo + r1 + cA + 16);
#pragma unroll
                for (int g = 0; g < 4; g++)
                    mma16816(C[g], alf, Bhi[g][kt]);
            }

#pragma unroll
            for (int kt = 0; kt < 4; kt++)
#pragma unroll
                for (int g = 0; g < 4; g++)
                    mma16816(C[g], ahf[kt], Blo[g][kt]);

            {
                uint32_t axf[4];
                const int rx0 = (mt * 16 + gl) * (AXSTR * 2);
                const int rx1 = (mt * 16 + gl + 8) * (AXSTR * 2);
                const int cX = t2 * 2;
                axf[0] = *(const uint32_t*)(ax + rx0 + cX);
                axf[1] = *(const uint32_t*)(ax + rx1 + cX);
                axf[2] = *(const uint32_t*)(ax + rx0 + cX + 16);
                axf[3] = *(const uint32_t*)(ax + rx1 + cX + 16);
#pragma unroll
                for (int g = 0; g < 4; g++)
                    mma16816(C[g], axf, Bx[g]);
            }

            float hv[4];
#pragma unroll
            for (int e = 0; e < 4; e++) {
                const float cn = sigf(C[1][e]) * cst[mt][e] + sigf(C[0][e]) * tanhf_(C[2][e]);
                cst[mt][e] = cn;
                hv[e] = sigf(C[3][e]) * tanhf_(cn);
            }

            if (!last) {
                ush h0b, l0b, h1b, l1b;
                const int off0 = r0 + dlo * 2;
                const int off1 = r1 + dlo * 2;
                split_bf(hv[0], h0b, l0b);
                split_bf(hv[1], h1b, l1b);
                *(uint32_t*)(nhi + off0) = pk(h0b, h1b);
                *(uint32_t*)(nlo + off0) = pk(l0b, l1b);
                split_bf(hv[2], h0b, l0b);
                split_bf(hv[3], h1b, l1b);
                *(uint32_t*)(nhi + off1) = pk(h0b, h1b);
                *(uint32_t*)(nlo + off1) = pk(l0b, l1b);
            } else {
                float* o0 = out + (size_t)(pb + mt * 16 + gl) * DCOL;
                float* o1 = out + (size_t)(pb + mt * 16 + gl + 8) * DCOL;
                *(float2*)&o0[cb + dlo]       = make_float2(hv[0], hv[1]);
                *(float2*)&o1[cb + dlo]       = make_float2(hv[2], hv[3]);
                *(float2*)&o0[128 + cb + dlo] = make_float2(cst[mt][0], cst[mt][1]);
                *(float2*)&o1[128 + cb + dlo] = make_float2(cst[mt][2], cst[mt][3]);
            }
        }
        __syncthreads();
    }
}

// ---------------------------------------------------------------------------
// K2: per-scene attention pooling on HMMA (split-bf16, ldmatrix).
// grid = S blocks, 256 threads. 1 scene per block (P=64, D=256).
// ---------------------------------------------------------------------------
#define EPAD 264
#define GPAD 68
#define PPAD 72
#define OFF_EHI 0
#define OFF_ELO (64 * EPAD * 2)            // 33792
#define OFF_PHI (OFF_ELO + 64 * EPAD * 2)  // 67584
#define OFF_PLO (OFF_PHI + 64 * PPAD * 2)  // 76800
#define OFF_GR  (OFF_PLO + 64 * PPAD * 2)  // 86016
#define SMEM_ATTN (OFF_GR + 64 * GPAD * 4) // 103424

__global__ void __launch_bounds__(TPB) attn_mma_kernel(float* __restrict__ out,
                                                       const float* __restrict__ obs)
{
    extern __shared__ char sm[];
    const uint32_t sb = smem_u32(sm);
    const int tid = threadIdx.x, w = tid >> 5, lane = tid & 31;
    const int pbase = blockIdx.x * 64;

    // ---- load E (64x256 f32) -> split bf16 hi/lo tiles ----
    for (int i = tid; i < 64 * 64; i += TPB) {
        const int p = i >> 6, c4 = i & 63;
        const float4 v = ((const float4*)(out + (size_t)(pbase + p) * DCOL))[c4];
        ush h0, l0, h1, l1, h2, l2, h3, l3;
        split_bf(v.x, h0, l0); split_bf(v.y, h1, l1);
        split_bf(v.z, h2, l2); split_bf(v.w, h3, l3);
        const int off = (p * EPAD + c4 * 4) * 2;
        *(uint2*)(sm + OFF_EHI + off) = make_uint2(pk(h0, h1), pk(h2, h3));
        *(uint2*)(sm + OFF_ELO + off) = make_uint2(pk(l0, l1), pk(l2, l3));
    }
    __syncthreads();

    // ---- gram: G = E E^T (64x64), warp w: m-tile w>>1, n-tiles (w&1)*2, +1 ----
    {
        const int mi = w >> 1, nbase = (w & 1) * 2;
        float C[2][2][4];
#pragma unroll
        for (int a = 0; a < 2; a++)
#pragma unroll
            for (int b = 0; b < 2; b++)
#pragma unroll
                for (int e = 0; e < 4; e++) C[a][b][e] = 0.f;

        const uint32_t arow = (uint32_t)((mi * 16 + (lane & 15)) * EPAD) * 2;
        const uint32_t brow0 = (uint32_t)(((nbase    ) * 16 + (lane & 15)) * EPAD) * 2;
        const uint32_t brow1 = (uint32_t)(((nbase + 1) * 16 + (lane & 15)) * EPAD) * 2;

#pragma unroll 4
        for (int kt = 0; kt < 16; kt++) {
            const uint32_t col = (uint32_t)(kt * 16 + (lane >> 4) * 8) * 2;
            uint32_t ah[4], al[4];
            ldsm4(ah, sb + OFF_EHI + arow + col);
            ldsm4(al, sb + OFF_ELO + arow + col);
#pragma unroll
            for (int n2 = 0; n2 < 2; n2++) {
                const uint32_t brow = n2 ? brow1 : brow0;
                uint32_t bh[4], bl[4];
                ldsm4(bh, sb + OFF_EHI + brow + col);
                ldsm4(bl, sb + OFF_ELO + brow + col);
#pragma unroll
                for (int nb = 0; nb < 2; nb++) {
                    uint32_t bhp[2] = { bh[nb], bh[2 + nb] };
                    uint32_t blp[2] = { bl[nb], bl[2 + nb] };
                    mma16816(C[n2][nb], ah, bhp);
                    mma16816(C[n2][nb], al, bhp);
                    mma16816(C[n2][nb], ah, blp);
                }
            }
        }
        float* gr = (float*)(sm + OFF_GR);
        const int m0 = mi * 16 + (lane >> 2);
#pragma unroll
        for (int n2 = 0; n2 < 2; n2++)
#pragma unroll
            for (int nb = 0; nb < 2; nb++) {
                const int n0 = (nbase + n2) * 16 + nb * 8 + (lane & 3) * 2;
                *(float2*)&gr[m0 * GPAD + n0]       = make_float2(C[n2][nb][0], C[n2][nb][1]);
                *(float2*)&gr[(m0 + 8) * GPAD + n0] = make_float2(C[n2][nb][2], C[n2][nb][3]);
            }
    }
    __syncthreads();

    // ---- softmax rows ----
    if (tid < 64) {
        float* gr = (float*)(sm + OFF_GR) + tid * GPAD;
        float m = -1e30f;
        for (int q = 0; q < 64; q++) m = fmaxf(m, gr[q]);
        float ssum = 0.f;
        for (int q = 0; q < 64; q++) {
            const float e = __expf(gr[q] - m);
            gr[q] = e;
            ssum += e;
        }
        const float inv = __fdividef(1.0f, ssum);
        for (int q = 0; q < 64; q++) gr[q] *= inv;
    }
    __syncthreads();

    // ---- split P to bf16 hi/lo ----
    {
        const int p = tid >> 2, q0 = (tid & 3) * 16;
        const float* gr = (const float*)(sm + OFF_GR) + p * GPAD + q0;
#pragma unroll
        for (int j = 0; j < 8; j++) {
            ush h0, l0, h1, l1;
            split_bf(gr[j * 2],     h0, l0);
            split_bf(gr[j * 2 + 1], h1, l1);
            const int off = (p * PPAD + q0 + j * 2) * 2;
            *(uint32_t*)(sm + OFF_PHI + off) = pk(h0, h1);
            *(uint32_t*)(sm + OFF_PLO + off) = pk(l0, l1);
        }
    }
    __syncthreads();

    // ---- pool = P @ E (64x256), warp w: m-tile w>>1, d-half w&1 ----
    {
        const int mi = w >> 1, dh = w & 1;
        uint32_t ph[4][4], pl[4][4];
        const uint32_t prow = (uint32_t)((mi * 16 + (lane & 15)) * PPAD) * 2;
#pragma unroll
        for (int kt = 0; kt < 4; kt++) {
            const uint32_t col = (uint32_t)(kt * 16 + (lane >> 4) * 8) * 2;
            ldsm4(ph[kt], sb + OFF_PHI + prow + col);
            ldsm4(pl[kt], sb + OFF_PLO + prow + col);
        }
        const int m0 = pbase + mi * 16 + (lane >> 2);
#pragma unroll 1
        for (int nt = 0; nt < 8; nt++) {
            const int ni = dh * 8 + nt;
            float C[2][4];
#pragma unroll
            for (int nb = 0; nb < 2; nb++)
#pragma unroll
                for (int e = 0; e < 4; e++) C[nb][e] = 0.f;
#pragma unroll
            for (int kt = 0; kt < 4; kt++) {
                const uint32_t baddr = sb + OFF_EHI +
                    (uint32_t)((kt * 16 + (lane & 15)) * EPAD + ni * 16 + (lane >> 4) * 8) * 2;
                uint32_t bh[4], bl[4];
                ldsm4t(bh, baddr);
                ldsm4t(bl, baddr + (OFF_ELO - OFF_EHI));
#pragma unroll
                for (int nb = 0; nb < 2; nb++) {
                    uint32_t bhp[2] = { bh[2 * nb], bh[2 * nb + 1] };
                    uint32_t blp[2] = { bl[2 * nb], bl[2 * nb + 1] };
                    mma16816(C[nb], ph[kt], bhp);
                    mma16816(C[nb], pl[kt], bhp);
                    mma16816(C[nb], ph[kt], blp);
                }
            }
#pragma unroll
            for (int nb = 0; nb < 2; nb++) {
                const int n0 = 256 + ni * 16 + nb * 8 + (lane & 3) * 2;
                *(float2*)&out[(size_t)m0 * DCOL + n0]       = make_float2(C[nb][0], C[nb][1]);
                *(float2*)&out[(size_t)(m0 + 8) * DCOL + n0] = make_float2(C[nb][2], C[nb][3]);
            }
        }
    }

    // ---- obs_enc_feat copy ----
    for (int i = tid; i < 64 * MLPW; i += TPB) {
        const int p = i >> 5, cc = i & 31;
        out[(size_t)(pbase + p) * DCOL + 512 + cc] = obs[(size_t)(pbase + p) * MLPW + cc];
    }
}

// ---------------------------------------------------------------------------
// K3: stats = dist_fc_input @ w_fc2 + b_fc2 (R1 version, proven).
// ---------------------------------------------------------------------------
__global__ void __launch_bounds__(TPB) fc2_kernel(
    const float* __restrict__ dfi, const float* __restrict__ w,
    const float* __restrict__ bz, float* __restrict__ stats)
{
    extern __shared__ float ws[];
    const int tid = threadIdx.x;
    for (int i = tid; i < (DCOL * ZS) / 4; i += TPB)
        ((float4*)ws)[i] = ((const float4*)w)[i];
    __syncthreads();

    const int og = tid & 7, rl = tid >> 3;
    const int o0 = og * 4;
    const int rowbase = blockIdx.x * 256;

    for (int pass = 0; pass < 8; pass++) {
        const int row = rowbase + pass * 32 + rl;
        const float* dr = dfi + (size_t)row * DCOL;
        float a0 = bz[o0], a1 = bz[o0 + 1], a2 = bz[o0 + 2], a3 = bz[o0 + 3];
#pragma unroll 4
        for (int j = 0; j < DCOL; j++) {
            const float d = __ldg(dr + j);
            const float4 wv = *(const float4*)&ws[j * ZS + o0];
            a0 += d * wv.x; a1 += d * wv.y; a2 += d * wv.z; a3 += d * wv.w;
        }
        float* so = stats + (size_t)row * ZS + o0;
        so[0] = a0; so[1] = a1; so[2] = a2; so[3] = a3;
    }
}

// ---------------------------------------------------------------------------
extern "C" void kernel_launch(void* const* d_in, const int* in_sizes, int n_in,
                              void* d_out, int out_size)
{
    const float* last_obs = (const float*)d_in[0];
    const float* xseq     = (const float*)d_in[1];
    const float* obs      = (const float*)d_in[3];
    const float* w_h0     = (const float*)d_in[5];
    const float* b_h0     = (const float*)d_in[6];
    const float* w_c0     = (const float*)d_in[7];
    const float* b_c0     = (const float*)d_in[8];
    const float* w_ih_f   = (const float*)d_in[9];
    const float* w_hh_f   = (const float*)d_in[10];
    const float* b_f      = (const float*)d_in[11];
    const float* w_ih_r   = (const float*)d_in[12];
    const float* w_hh_r   = (const float*)d_in[13];
    const float* b_r      = (const float*)d_in[14];
    const float* w_fc2    = (const float*)d_in[15];
    const float* b_fc2    = (const float*)d_in[16];
    float* out = (float*)d_out;

    const int B = in_sizes[0] / 6;
    const int T = in_sizes[1] / (B * 2);
    const int S = in_sizes[2] / 2;

    const int smem_fc2 = DCOL * ZS * 4;

    cudaFuncSetAttribute(lstm_mma_kernel, cudaFuncAttributeMaxDynamicSharedMemorySize, SMEM_LSTM);
    cudaFuncSetAttribute(attn_mma_kernel, cudaFuncAttributeMaxDynamicSharedMemorySize, SMEM_ATTN);
    cudaFuncSetAttribute(fc2_kernel,  cudaFuncAttributeMaxDynamicSharedMemorySize, smem_fc2);

    dim3 g1(B / 128, 2);
    lstm_mma_kernel<<<g1, TPB, SMEM_LSTM>>>(last_obs, xseq,
                                            w_h0, b_h0, w_c0, b_c0,
                                            w_ih_f, w_hh_f, b_f,
                                            w_ih_r, w_hh_r, b_r,
                                            out, B, T);

    attn_mma_kernel<<<S, TPB, SMEM_ATTN>>>(out, obs);

    float* stats = out + (size_t)B * DCOL;
    fc2_kernel<<<B / 256, TPB, smem_fc2>>>(out, w_fc2, b_fc2, stats);
}